// round 1
// baseline (speedup 1.0000x reference)
#include <cuda_runtime.h>
#include <math.h>

// ============================================================================
// ExponentialConcordanceLoss via O(N) bucketed counting sort.
//
// loss = ( sum_{i,j: t[j]<t[i], e[j], finite both} exp(s[i]-s[j]) ) / max(cnt,1)
// Separable: total = sum_i a[i] * S_i,
//   a[i]  = finite[i] ? exp(s[i]) : 0
//   b0[j] = (finite[j] && e[j]) ? exp(-s[j]) : 0
//   S_i   = sum of b0[j] over all j with t[j] < t[i]   (strict)
// count = sum_i finite[i] * (# of j with t[j] < t[i], e[j], finite[j])
//
// Strict order statistic handled by 8192 buckets over [tmin,tmax]:
//   bucket index monotone in t -> lower buckets via exclusive prefix sums;
//   same-bucket pairs resolved exactly against original t (handles ties and
//   any distribution; only slow if everything lands in one bucket).
// Counts are integers end-to-end (total can exceed 2^24).
// ============================================================================

#define NMAX   16384
#define KB     8192           // number of buckets
#define NBMAX  ((NMAX + 255) / 256)

__device__ float g_t[NMAX];
__device__ float g_b0[NMAX];
__device__ float g_a[NMAX];
__device__ int   g_c0[NMAX];
__device__ int   g_fin[NMAX];
__device__ int   g_bucket[NMAX];
__device__ int   g_pos[NMAX];
__device__ int   g_sortedIdx[NMAX];

__device__ int   g_histCnt[KB];
__device__ float g_histB0[KB];
__device__ int   g_histC0[KB];
__device__ int   g_bucketStart[KB];
__device__ float g_prefB0[KB];
__device__ int   g_prefC0[KB];

__device__ unsigned g_minK, g_maxK;

__device__ float     g_blockSum[NBMAX];
__device__ long long g_blockCnt[NBMAX];

// Order-preserving float <-> uint key (standard sign-flip transform)
__device__ __forceinline__ unsigned f2key(float f) {
    unsigned u = __float_as_uint(f);
    return (u & 0x80000000u) ? ~u : (u | 0x80000000u);
}
__device__ __forceinline__ float key2f(unsigned k) {
    unsigned u = (k & 0x80000000u) ? (k & 0x7fffffffu) : ~k;
    return __uint_as_float(u);
}

// ---------------------------------------------------------------------------
__global__ void k0_zero() {
    int i = blockIdx.x * blockDim.x + threadIdx.x;
    if (i < KB) {
        g_histCnt[i] = 0;
        g_histB0[i]  = 0.0f;
        g_histC0[i]  = 0;
    }
    if (i == 0) {
        g_minK = 0xFFFFFFFFu;
        g_maxK = 0u;
    }
}

// ---------------------------------------------------------------------------
__global__ void k1_prep(const float* __restrict__ preds,
                        const float* __restrict__ targets, int n) {
    int i = blockIdx.x * blockDim.x + threadIdx.x;
    if (i >= n) return;
    float s  = preds[i];
    float t  = targets[2 * i + 0];
    float ev = targets[2 * i + 1];
    bool fin = isfinite(t) && isfinite(s);
    bool e   = fin && (ev != 0.0f);

    g_t[i]   = t;
    g_b0[i]  = e ? __expf(-s) : 0.0f;
    g_c0[i]  = e ? 1 : 0;
    g_a[i]   = fin ? __expf(s) : 0.0f;
    g_fin[i] = fin ? 1 : 0;

    if (fin) {
        unsigned k = f2key(t);
        atomicMin(&g_minK, k);
        atomicMax(&g_maxK, k);
    }
}

// ---------------------------------------------------------------------------
__global__ void k2_hist(int n) {
    int i = blockIdx.x * blockDim.x + threadIdx.x;
    if (i >= n) return;

    float tmin  = key2f(g_minK);
    float tmax  = key2f(g_maxK);
    float range = tmax - tmin;
    float scale = (range > 0.0f) ? ((float)KB / range) : 0.0f;

    float t = g_t[i];
    float x = (t - tmin) * scale;   // NaN -> cvt.rzi -> 0; +/-inf saturate
    int b = (int)x;
    if (b < 0) b = 0;
    if (b > KB - 1) b = KB - 1;

    g_bucket[i] = b;
    g_pos[i]    = atomicAdd(&g_histCnt[b], 1);
    atomicAdd(&g_histB0[b], g_b0[i]);
    if (g_c0[i]) atomicAdd(&g_histC0[b], 1);
}

// ---------------------------------------------------------------------------
// Exclusive 3-way scan over KB=8192 buckets. One block of 1024 threads,
// 8 buckets per thread; Hillis-Steele over thread totals in shared.
__global__ void k3_scan() {
    __shared__ float     sB[1024];
    __shared__ int       sC[1024];
    __shared__ int       sN[1024];

    int tid  = threadIdx.x;
    int base = tid * 8;

    float lb[8]; int lc[8]; int ln[8];
    float rb = 0.0f; int rc = 0, rn = 0;
#pragma unroll
    for (int u = 0; u < 8; u++) {
        lb[u] = rb; lc[u] = rc; ln[u] = rn;
        rb += g_histB0[base + u];
        rc += g_histC0[base + u];
        rn += g_histCnt[base + u];
    }
    sB[tid] = rb; sC[tid] = rc; sN[tid] = rn;
    __syncthreads();

    for (int off = 1; off < 1024; off <<= 1) {
        float vb = 0.0f; int vc = 0, vn = 0;
        if (tid >= off) { vb = sB[tid - off]; vc = sC[tid - off]; vn = sN[tid - off]; }
        __syncthreads();
        sB[tid] += vb; sC[tid] += vc; sN[tid] += vn;
        __syncthreads();
    }

    float eb = (tid > 0) ? sB[tid - 1] : 0.0f;
    int   ec = (tid > 0) ? sC[tid - 1] : 0;
    int   en = (tid > 0) ? sN[tid - 1] : 0;

#pragma unroll
    for (int u = 0; u < 8; u++) {
        g_prefB0[base + u]      = eb + lb[u];
        g_prefC0[base + u]      = ec + lc[u];
        g_bucketStart[base + u] = en + ln[u];
    }
}

// ---------------------------------------------------------------------------
__global__ void k4_scatter(int n) {
    int i = blockIdx.x * blockDim.x + threadIdx.x;
    if (i >= n) return;
    g_sortedIdx[g_bucketStart[g_bucket[i]] + g_pos[i]] = i;
}

// ---------------------------------------------------------------------------
__global__ void k5_main(int n) {
    int tid = threadIdx.x;
    int i   = blockIdx.x * blockDim.x + tid;

    float     ts = 0.0f;
    long long tc = 0;
    if (i < n) {
        int   k   = g_bucket[i];
        float S   = g_prefB0[k];
        int   C   = g_prefC0[k];
        int   st  = g_bucketStart[k];
        int   cnt = g_histCnt[k];
        float ti  = g_t[i];
        for (int m = st; m < st + cnt; m++) {
            int j = g_sortedIdx[m];
            if (g_t[j] < ti) {      // strict; excludes i itself & ties
                S += g_b0[j];
                C += g_c0[j];
            }
        }
        ts = g_a[i] * S;
        tc = g_fin[i] ? (long long)C : 0;
    }

    __shared__ float     sS[256];
    __shared__ long long sC2[256];
    sS[tid]  = ts;
    sC2[tid] = tc;
    __syncthreads();
    for (int off = 128; off > 0; off >>= 1) {
        if (tid < off) {
            sS[tid]  += sS[tid + off];
            sC2[tid] += sC2[tid + off];
        }
        __syncthreads();
    }
    if (tid == 0) {
        g_blockSum[blockIdx.x] = sS[0];
        g_blockCnt[blockIdx.x] = sC2[0];
    }
}

// ---------------------------------------------------------------------------
__global__ void k6_final(float* __restrict__ out, int nblocks) {
    __shared__ float     sS[64];
    __shared__ long long sC[64];
    int tid = threadIdx.x;
    float     s = 0.0f;
    long long c = 0;
    for (int b = tid; b < nblocks; b += 64) {
        s += g_blockSum[b];
        c += g_blockCnt[b];
    }
    sS[tid] = s; sC[tid] = c;
    __syncthreads();
    for (int off = 32; off > 0; off >>= 1) {
        if (tid < off) { sS[tid] += sS[tid + off]; sC[tid] += sC[tid + off]; }
        __syncthreads();
    }
    if (tid == 0) {
        float denom = fmaxf((float)sC[0], 1.0f);
        out[0] = sS[0] / denom;
    }
}

// ---------------------------------------------------------------------------
extern "C" void kernel_launch(void* const* d_in, const int* in_sizes, int n_in,
                              void* d_out, int out_size) {
    const float* preds   = (const float*)d_in[0];
    const float* targets = (const float*)d_in[1];
    int n = in_sizes[0];
    if (n > NMAX) n = NMAX;
    int nb = (n + 255) / 256;

    k0_zero   <<<(KB + 255) / 256, 256>>>();
    k1_prep   <<<nb, 256>>>(preds, targets, n);
    k2_hist   <<<nb, 256>>>(n);
    k3_scan   <<<1, 1024>>>();
    k4_scatter<<<nb, 256>>>(n);
    k5_main   <<<nb, 256>>>(n);
    k6_final  <<<1, 64>>>((float*)d_out, nb);
}

// round 2
// speedup vs baseline: 1.4125x; 1.4125x over previous
#include <cuda_runtime.h>
#include <math.h>

// ============================================================================
// ExponentialConcordanceLoss, O(N), fully fused into ONE persistent kernel
// with software grid barriers (single-wave grid: nb<=64 blocks of 256).
//
// loss = ( sum_{i,j: t[j]<t[i], e[j], finite both} exp(s[i]-s[j]) ) / max(cnt,1)
//   a[i]  = finite[i] ? exp(s[i]) : 0
//   b0[j] = (finite[j] && e[j]) ? exp(-s[j]) : 0
//   total = sum_i a[i] * (sum of b0[j] over t[j]<t[i])
// Strict order handled by 2048 monotone buckets + exact same-bucket compares.
// Counts are integers end-to-end. Cross-block reads use __ldcg (L2-coherent).
// ============================================================================

#define NMAX  16384
#define KB    2048
#define KPT   8          // buckets per thread in the 256-thread scan (KB/256)
#define NBMAX 64

__device__ float g_t[NMAX];
__device__ float g_b0[NMAX];
__device__ float g_a[NMAX];
__device__ int   g_c0[NMAX];
__device__ int   g_fin[NMAX];
__device__ int   g_bucket[NMAX];
__device__ int   g_pos[NMAX];
__device__ int   g_sortedIdx[NMAX];

__device__ int   g_histCnt[KB];
__device__ float g_histB0[KB];
__device__ int   g_histC0[KB];
__device__ int   g_bucketStart[KB];
__device__ float g_prefB0[KB];
__device__ int   g_prefC0[KB];

__device__ float     g_blkMin[NBMAX];
__device__ float     g_blkMax[NBMAX];
__device__ float     g_blockSum[NBMAX];
__device__ long long g_blockCnt[NBMAX];
__device__ unsigned  g_barCount;   // zero at module load; reset at end of run

// Grid barrier: monotonically increasing targets (nb, 2nb, 3nb, ...).
// Standard cooperative-groups pattern; safe because grid is one wave.
__device__ __forceinline__ void gbar(unsigned target) {
    __syncthreads();
    if (threadIdx.x == 0) {
        __threadfence();                       // release
        atomicAdd(&g_barCount, 1u);
        while (atomicAdd(&g_barCount, 0u) < target) __nanosleep(20);
        __threadfence();                       // acquire
    }
    __syncthreads();
}

__global__ void __launch_bounds__(256, 1)
fused_kernel(const float* __restrict__ preds,
             const float* __restrict__ targets,
             float* __restrict__ out,
             int n, int nb) {
    const int tid  = threadIdx.x;
    const int bid  = blockIdx.x;
    const int i    = bid * 256 + tid;
    const int lane = tid & 31;
    const int warp = tid >> 5;
    const unsigned NB = (unsigned)nb;

    __shared__ float sMn[8], sMx[8];
    __shared__ float s_minv, s_maxv;
    __shared__ float     sRed[256];
    __shared__ long long sCnt[256];

    // ---------------- Phase A: zero hist; per-element prep; block min/max ---
    for (int h = i; h < KB; h += nb * 256) {
        g_histCnt[h] = 0; g_histB0[h] = 0.0f; g_histC0[h] = 0;
    }

    float tmn = __int_as_float(0x7f800000);   // +inf
    float tmx = -tmn;
    if (i < n) {
        float s   = preds[i];
        float2 tg = ((const float2*)targets)[i];
        float tv  = tg.x;
        float ev  = tg.y;
        bool fin = isfinite(tv) && isfinite(s);
        bool e   = fin && (ev != 0.0f);
        g_t[i]   = tv;
        g_b0[i]  = e ? __expf(-s) : 0.0f;
        g_c0[i]  = e ? 1 : 0;
        g_a[i]   = fin ? __expf(s) : 0.0f;
        g_fin[i] = fin ? 1 : 0;
        if (fin) { tmn = tv; tmx = tv; }
    }
#pragma unroll
    for (int o = 16; o > 0; o >>= 1) {
        tmn = fminf(tmn, __shfl_xor_sync(0xffffffffu, tmn, o));
        tmx = fmaxf(tmx, __shfl_xor_sync(0xffffffffu, tmx, o));
    }
    if (lane == 0) { sMn[warp] = tmn; sMx[warp] = tmx; }
    __syncthreads();
    if (tid == 0) {
        float a = sMn[0], b = sMx[0];
#pragma unroll
        for (int w = 1; w < 8; w++) { a = fminf(a, sMn[w]); b = fmaxf(b, sMx[w]); }
        g_blkMin[bid] = a; g_blkMax[bid] = b;
    }
    gbar(NB);

    // ---------------- Phase B: global min/max; histogram ---------------------
    if (tid < 32) {
        float a = __int_as_float(0x7f800000), b = -a;
        for (int bb = lane; bb < nb; bb += 32) {
            a = fminf(a, __ldcg(&g_blkMin[bb]));
            b = fmaxf(b, __ldcg(&g_blkMax[bb]));
        }
#pragma unroll
        for (int o = 16; o > 0; o >>= 1) {
            a = fminf(a, __shfl_xor_sync(0xffffffffu, a, o));
            b = fmaxf(b, __shfl_xor_sync(0xffffffffu, b, o));
        }
        if (lane == 0) { s_minv = a; s_maxv = b; }
    }
    __syncthreads();
    {
        float tmin  = s_minv;
        float range = s_maxv - tmin;
        float scale = (range > 0.0f) ? ((float)KB / range) : 0.0f;
        if (i < n) {
            float tv = g_t[i];
            float x  = (tv - tmin) * scale;    // NaN -> 0 after cvt; clamp below
            int bkt = (int)x;
            bkt = max(0, min(KB - 1, bkt));
            g_bucket[i] = bkt;
            g_pos[i]    = atomicAdd(&g_histCnt[bkt], 1);
            atomicAdd(&g_histB0[bkt], g_b0[i]);
            if (g_c0[i]) atomicAdd(&g_histC0[bkt], 1);
        }
    }
    gbar(2u * NB);

    // ---------------- Phase C: 3-way exclusive scan (block 0, 256 thr) ------
    if (bid == 0) {
        const int base = tid * KPT;
        float lb[KPT]; int lc[KPT]; int ln[KPT];
        float rb = 0.0f; int rc = 0, rn = 0;
#pragma unroll
        for (int u = 0; u < KPT; u++) {
            lb[u] = rb; lc[u] = rc; ln[u] = rn;
            rb += __ldcg(&g_histB0[base + u]);
            rc += __ldcg(&g_histC0[base + u]);
            rn += __ldcg(&g_histCnt[base + u]);
        }
        float Tt = rb; int Tc = rc, Tn = rn;       // thread totals
#pragma unroll
        for (int o = 1; o < 32; o <<= 1) {          // warp inclusive scan
            float vb = __shfl_up_sync(0xffffffffu, rb, o);
            int   vc = __shfl_up_sync(0xffffffffu, rc, o);
            int   vn = __shfl_up_sync(0xffffffffu, rn, o);
            if (lane >= o) { rb += vb; rc += vc; rn += vn; }
        }
        __shared__ float wB[8]; __shared__ int wC[8], wN[8];
        if (lane == 31) { wB[warp] = rb; wC[warp] = rc; wN[warp] = rn; }
        __syncthreads();
        float offB = 0.0f; int offC = 0, offN = 0;
        for (int w = 0; w < warp; w++) { offB += wB[w]; offC += wC[w]; offN += wN[w]; }
        float eb = offB + rb - Tt;                  // exclusive thread prefix
        int   ec = offC + rc - Tc;
        int   en = offN + rn - Tn;
#pragma unroll
        for (int u = 0; u < KPT; u++) {
            g_prefB0[base + u]      = eb + lb[u];
            g_prefC0[base + u]      = ec + lc[u];
            g_bucketStart[base + u] = en + ln[u];
        }
    }
    gbar(3u * NB);

    // ---------------- Phase D: scatter into bucket-sorted order -------------
    if (i < n) {
        g_sortedIdx[__ldcg(&g_bucketStart[g_bucket[i]]) + g_pos[i]] = i;
    }
    gbar(4u * NB);

    // ---------------- Phase E: per-element sums + block reduce ---------------
    float     ts = 0.0f;
    long long tc = 0;
    if (i < n) {
        int   k   = g_bucket[i];
        float S   = __ldcg(&g_prefB0[k]);
        int   C   = __ldcg(&g_prefC0[k]);
        int   st  = __ldcg(&g_bucketStart[k]);
        int   cnt = __ldcg(&g_histCnt[k]);
        float ti  = g_t[i];
        for (int m = st; m < st + cnt; m++) {
            int   j  = __ldcg(&g_sortedIdx[m]);
            float tj = __ldcg(&g_t[j]);
            if (tj < ti) {                      // strict: excludes self & ties
                S += __ldcg(&g_b0[j]);
                C += __ldcg(&g_c0[j]);
            }
        }
        ts = g_a[i] * S;
        tc = g_fin[i] ? (long long)C : 0;
    }
    sRed[tid] = ts; sCnt[tid] = tc;
    __syncthreads();
    for (int off = 128; off > 0; off >>= 1) {
        if (tid < off) { sRed[tid] += sRed[tid + off]; sCnt[tid] += sCnt[tid + off]; }
        __syncthreads();
    }

    // One-way arrive; block 0 thread 0 finalizes deterministically and resets.
    if (tid == 0) {
        g_blockSum[bid] = sRed[0];
        g_blockCnt[bid] = sCnt[0];
        __threadfence();
        atomicAdd(&g_barCount, 1u);
        if (bid == 0) {
            while (atomicAdd(&g_barCount, 0u) < 5u * NB) __nanosleep(20);
            __threadfence();
            float     s = 0.0f;
            long long c = 0;
            for (int b2 = 0; b2 < nb; b2++) {
                s += __ldcg(&g_blockSum[b2]);
                c += __ldcg(&g_blockCnt[b2]);
            }
            out[0] = s / fmaxf((float)c, 1.0f);
            atomicExch(&g_barCount, 0u);        // reset for next graph replay
        }
    }
}

// ---------------------------------------------------------------------------
extern "C" void kernel_launch(void* const* d_in, const int* in_sizes, int n_in,
                              void* d_out, int out_size) {
    const float* preds   = (const float*)d_in[0];
    const float* targets = (const float*)d_in[1];
    int n = in_sizes[0];
    if (n > NMAX) n = NMAX;
    int nb = (n + 255) / 256;
    if (nb < 1) nb = 1;
    fused_kernel<<<nb, 256>>>(preds, targets, (float*)d_out, n, nb);
}